// round 9
// baseline (speedup 1.0000x reference)
#include <cuda_runtime.h>
#include <cstdint>

// Shapes (fixed by the problem)
#define Bq   256
#define Tq   512
#define Vq   100000
#define Eq   128
#define Hq   256
#define G3   768            // 3*H
#define XPW  1536           // 2 * 3H (forward | backward packed)
#define NTOK (Bq * Tq)      // 131072

// ---------------- scratch (static device globals; no runtime allocation) ---
__device__ float  g_xp[(size_t)NTOK * XPW];          // [T][B][1536]  (805 MB)
__device__ float4 g_wih4[(Eq / 4) * XPW];            // [32][1536] float4  (packed W_ih, k-blocked)
__device__ float4 g_whh4[2 * (Hq / 4) * G3];         // [2][64][768] float4 (packed W_hh, k-blocked)
__device__ float  g_hcat[Bq * 2 * Hq];               // [B][512] concat(hf, hb)

// ---------------- helpers --------------------------------------------------
__device__ __forceinline__ float sigmoid_f(float x) {
    // exp overflow is benign: 1/(1+inf)=0, 1/(1+0)=1
    return 1.0f / (1.0f + __expf(-x));
}
__device__ __forceinline__ float tanh_f(float x) {
    x = fminf(15.0f, fmaxf(-15.0f, x));      // avoid inf/inf; tanh saturated anyway
    float e = __expf(2.0f * x);
    return (e - 1.0f) / (e + 1.0f);
}

// ---------------- K0: pack weights into k-blocked float4 layout ------------
// g_wih4[kb*1536 + out].{x,y,z,w} = W_ih(out)[kb*4 + 0..3]   (out<768: fwd, else bwd)
// g_whh4[(d*64 + kb)*768 + out]   = W_hh_d(out)[kb*4 + 0..3]
__global__ void pack_kernel(const float* __restrict__ wih_f, const float* __restrict__ wih_b,
                            const float* __restrict__ whh_f, const float* __restrict__ whh_b) {
    int i = blockIdx.x * blockDim.x + threadIdx.x;
    const int n_ih = XPW * Eq;          // 196608
    const int n_hh = 2 * G3 * Hq;       // 393216
    if (i < n_ih) {
        int out = i / Eq, k = i % Eq;
        float v = (out < G3) ? wih_f[out * Eq + k] : wih_b[(out - G3) * Eq + k];
        ((float*)g_wih4)[((k >> 2) * XPW + out) * 4 + (k & 3)] = v;
    } else if (i < n_ih + n_hh) {
        int j = i - n_ih;
        int d = j / (G3 * Hq);
        int rem = j % (G3 * Hq);
        int out = rem / Hq, k = rem % Hq;
        const float* w = d ? whh_b : whh_f;
        ((float*)g_whh4)[((d * (Hq / 4) + (k >> 2)) * G3 + out) * 4 + (k & 3)] = w[out * Hq + k];
    }
}

// ---------------- K1: embedding gather + input projection ------------------
// Per CTA: 16 tokens x 1536 outputs, K=128. Thread j owns outputs {g*256+j}.
// W streamed coalesced from L2 (float4), embeddings staged in smem (broadcast reads).
__global__ void __launch_bounds__(256) proj_kernel(const int* __restrict__ x,
                                                   const float* __restrict__ emb,
                                                   const float* __restrict__ bih_f,
                                                   const float* __restrict__ bih_b) {
    __shared__ __align__(16) float s_emb[16][Eq];
    __shared__ int s_vid[16];
    const int tid = threadIdx.x;
    const int tok0 = blockIdx.x * 16;

    if (tid < 16) {
        int tok = tok0 + tid;
        int b = tok & (Bq - 1);
        int t = tok >> 8;
        s_vid[tid] = x[b * Tq + t];
    }
    __syncthreads();
#pragma unroll
    for (int i = 0; i < 8; ++i) {
        int idx = tid + i * 256;        // 2048 = 16 rows * 128
        int m = idx >> 7, k = idx & 127;
        s_emb[m][k] = emb[(size_t)s_vid[m] * Eq + k];
    }
    __syncthreads();

    const int j = tid;
    float acc[6][16];
#pragma unroll
    for (int g = 0; g < 6; ++g) {
        int out = g * 256 + j;
        float bv = (out < G3) ? bih_f[out] : bih_b[out - G3];
#pragma unroll
        for (int m = 0; m < 16; ++m) acc[g][m] = bv;
    }

#pragma unroll 2
    for (int kb = 0; kb < Eq / 4; ++kb) {
        float4 w[6];
#pragma unroll
        for (int g = 0; g < 6; ++g) w[g] = g_wih4[kb * XPW + g * 256 + j];
#pragma unroll
        for (int m = 0; m < 16; ++m) {
            float4 e = *(const float4*)&s_emb[m][kb * 4];
#pragma unroll
            for (int g = 0; g < 6; ++g) {
                acc[g][m] += w[g].x * e.x + w[g].y * e.y + w[g].z * e.z + w[g].w * e.w;
            }
        }
    }

#pragma unroll
    for (int m = 0; m < 16; ++m) {
        float* dst = &g_xp[(size_t)(tok0 + m) * XPW];
#pragma unroll
        for (int g = 0; g < 6; ++g) dst[g * 256 + j] = acc[g][m];
    }
}

// ---------------- K2: GRU recurrence (persistent, batch-partitioned) -------
// Grid 128: dir = blk>>6, 4 batch rows per CTA. 256 threads; thread j owns
// hidden unit j (gate rows j, 256+j, 512+j). h lives in smem; W streamed from L2.
__global__ void __launch_bounds__(256) gru_kernel(const int* __restrict__ lengths,
                                                  const float* __restrict__ bhh_f,
                                                  const float* __restrict__ bhh_b) {
    __shared__ __align__(16) float hs[4][Hq];
    const int tid = threadIdx.x;
    const int dir = blockIdx.x >> 6;
    const int b0 = (blockIdx.x & 63) * 4;

    const float4* __restrict__ W4 = g_whh4 + dir * (Hq / 4) * G3;
    const float* __restrict__ bhh = dir ? bhh_b : bhh_f;

    int len[4];
#pragma unroll
    for (int r = 0; r < 4; ++r) len[r] = lengths[b0 + r];

    for (int i = tid; i < 4 * Hq; i += 256) ((float*)hs)[i] = 0.0f;
    const float br = bhh[tid], bz = bhh[256 + tid], bn = bhh[512 + tid];
    __syncthreads();

    int t = dir ? (Tq - 1) : 0;
    const int stp = dir ? -1 : 1;

    for (int it = 0; it < Tq; ++it, t += stp) {
        // precomputed input projections for this step (in flight during k-loop)
        float xr[4], xz[4], xn[4];
#pragma unroll
        for (int r = 0; r < 4; ++r) {
            const float* xq = &g_xp[(size_t)(t * Bq + b0 + r) * XPW + dir * G3];
            xr[r] = xq[tid];
            xz[r] = xq[256 + tid];
            xn[r] = xq[512 + tid];
        }

        float ar[4] = {br, br, br, br};
        float az[4] = {bz, bz, bz, bz};
        float an[4] = {bn, bn, bn, bn};

#pragma unroll 4
        for (int kb = 0; kb < Hq / 4; ++kb) {
            float4 wr = W4[kb * G3 + tid];
            float4 wz = W4[kb * G3 + 256 + tid];
            float4 wn = W4[kb * G3 + 512 + tid];
#pragma unroll
            for (int r = 0; r < 4; ++r) {
                float4 h4 = *(const float4*)&hs[r][kb * 4];   // smem broadcast
                ar[r] += wr.x * h4.x + wr.y * h4.y + wr.z * h4.z + wr.w * h4.w;
                az[r] += wz.x * h4.x + wz.y * h4.y + wz.z * h4.z + wz.w * h4.w;
                an[r] += wn.x * h4.x + wn.y * h4.y + wn.z * h4.z + wn.w * h4.w;
            }
        }

        float hn_[4];
#pragma unroll
        for (int r = 0; r < 4; ++r) {
            float rg = sigmoid_f(xr[r] + ar[r]);
            float zg = sigmoid_f(xz[r] + az[r]);
            float ng = tanh_f(xn[r] + rg * an[r]);
            float hold = hs[r][tid];
            hn_[r] = (t < len[r]) ? ((1.0f - zg) * ng + zg * hold) : hold;
        }
        __syncthreads();   // everyone done READING hs for this step
#pragma unroll
        for (int r = 0; r < 4; ++r) hs[r][tid] = hn_[r];
        __syncthreads();   // hs updated before next step reads
    }

#pragma unroll
    for (int r = 0; r < 4; ++r)
        g_hcat[(b0 + r) * (2 * Hq) + dir * Hq + tid] = hs[r][tid];
}

// ---------------- K3: fc1 + relu + fc2 + L2 normalize ----------------------
__global__ void __launch_bounds__(256) head_kernel(const float* __restrict__ fc1_w,
                                                   const float* __restrict__ fc1_b,
                                                   const float* __restrict__ fc2_w,
                                                   const float* __restrict__ fc2_b,
                                                   float* __restrict__ out) {
    __shared__ float s_in[2 * Hq];
    __shared__ float s_hid[128];
    __shared__ float s_out[64];
    __shared__ float s_ss;
    const int b = blockIdx.x, tid = threadIdx.x;

    s_in[tid]       = g_hcat[b * 512 + tid];
    s_in[tid + 256] = g_hcat[b * 512 + 256 + tid];
    __syncthreads();

    const int w = tid >> 5, lane = tid & 31;
    // fc1: 128 outputs = 8 warps * 16, lane-strided K, shuffle reduce
#pragma unroll
    for (int i = 0; i < 16; ++i) {
        int o = w * 16 + i;
        float p = 0.0f;
#pragma unroll
        for (int m = 0; m < 16; ++m) {
            int k = lane + m * 32;
            p += s_in[k] * fc1_w[o * 512 + k];
        }
#pragma unroll
        for (int s = 16; s > 0; s >>= 1) p += __shfl_xor_sync(0xffffffffu, p, s);
        if (lane == 0) s_hid[o] = fmaxf(p + fc1_b[o], 0.0f);
    }
    __syncthreads();

    // fc2: 64 outputs on warps 0-1
    if (w < 2) {
#pragma unroll
        for (int i = 0; i < 32; ++i) {
            int o = w * 32 + i;
            float p = 0.0f;
#pragma unroll
            for (int m = 0; m < 4; ++m) {
                int k = lane + m * 32;
                p += s_hid[k] * fc2_w[o * 128 + k];
            }
#pragma unroll
            for (int s = 16; s > 0; s >>= 1) p += __shfl_xor_sync(0xffffffffu, p, s);
            if (lane == 0) s_out[o] = p + fc2_b[o];
        }
    }
    __syncthreads();

    if (w == 0) {
        float v = s_out[lane] * s_out[lane] + s_out[lane + 32] * s_out[lane + 32];
#pragma unroll
        for (int s = 16; s > 0; s >>= 1) v += __shfl_xor_sync(0xffffffffu, v, s);
        if (lane == 0) s_ss = v;
    }
    __syncthreads();

    if (tid < 64) out[b * 64 + tid] = s_out[tid] / fmaxf(sqrtf(s_ss), 1e-12f);
}

// ---------------- launch ----------------------------------------------------
extern "C" void kernel_launch(void* const* d_in, const int* in_sizes, int n_in,
                              void* d_out, int out_size) {
    (void)in_sizes; (void)n_in; (void)out_size;
    const int*   x        = (const int*)d_in[0];
    const int*   lengths  = (const int*)d_in[1];
    const float* embedding= (const float*)d_in[2];
    const float* w_ih_f   = (const float*)d_in[3];
    const float* w_hh_f   = (const float*)d_in[4];
    const float* b_ih_f   = (const float*)d_in[5];
    const float* b_hh_f   = (const float*)d_in[6];
    const float* w_ih_b   = (const float*)d_in[7];
    const float* w_hh_b   = (const float*)d_in[8];
    const float* b_ih_b   = (const float*)d_in[9];
    const float* b_hh_b   = (const float*)d_in[10];
    const float* fc1_w    = (const float*)d_in[11];
    const float* fc1_b    = (const float*)d_in[12];
    const float* fc2_w    = (const float*)d_in[13];
    const float* fc2_b    = (const float*)d_in[14];
    float* out = (float*)d_out;

    pack_kernel<<<(XPW * Eq + 2 * G3 * Hq + 255) / 256, 256>>>(w_ih_f, w_ih_b, w_hh_f, w_hh_b);
    proj_kernel<<<NTOK / 16, 256>>>(x, embedding, b_ih_f, b_ih_b);
    gru_kernel<<<128, 256>>>(lengths, b_hh_f, b_hh_b);
    head_kernel<<<Bq, 256>>>(fc1_w, fc1_b, fc2_w, fc2_b, out);
}